// round 6
// baseline (speedup 1.0000x reference)
#include <cuda_runtime.h>
#include <cuda_fp16.h>
#include <cstdint>

#define NN 50000
#define EE 800000
#define D  128
#define SCAN_CHUNK 1024
#define SCAN_BLOCKS ((NN + SCAN_CHUNK - 1) / SCAN_CHUNK)   // 49

// ---------------- scratch (no allocations allowed) ----------------
__device__ float  g_deg[NN];          // weighted in-degree
__device__ int    g_counts[NN];       // edge count per dst
__device__ int    g_off[NN + 1];      // CSR offsets
__device__ int    g_cursor[NN];       // running cursor for permutation
__device__ int    g_bsum[SCAN_BLOCKS];// per-chunk totals (then exclusive-scanned)
__device__ int    g_psrc[EE];         // permuted src per CSR slot
__device__ float  g_pnorm[EE];        // permuted norm per CSR slot
__device__ __half g_h[NN * D];        // projection output in fp16 (both layers)
__device__ float  g_agg[NN * D];      // layer-1 aggregation target (fp32)
__device__ int    g_is64;             // 1 if edge_index is int64

// ---------------- dtype detection ----------------
// int64 indices (< 50000) viewed as int32 pairs => odd words all zero.
__global__ void detect_kernel(const int* __restrict__ ei) {
    if (threadIdx.x == 0 && blockIdx.x == 0) {
        int is64 = 1;
        for (int i = 0; i < 64; i++) {
            if (ei[2 * i + 1] != 0) { is64 = 0; break; }
        }
        g_is64 = is64;
    }
}

__device__ __forceinline__ int2 load_edge(const void* ei, int e, int E, int is64) {
    if (is64) {
        const long long* p = (const long long*)ei;
        return make_int2((int)p[e], (int)p[E + e]);
    } else {
        const int* p = (const int*)ei;
        return make_int2(p[e], p[E + e]);
    }
}

// ---------------- zero deg + counts ----------------
__global__ void zero_kernel(int N) {
    int i = blockIdx.x * blockDim.x + threadIdx.x;
    if (i < N) { g_deg[i] = 0.0f; g_counts[i] = 0; }
}

// ---------------- deg + histogram in one edge pass ----------------
__global__ void deg_hist_kernel(const void* __restrict__ ei, const float* __restrict__ ew, int E) {
    int e = blockIdx.x * blockDim.x + threadIdx.x;
    if (e >= E) return;
    int is64 = g_is64;
    int dst = is64 ? (int)((const long long*)ei)[E + e] : ((const int*)ei)[E + e];
    atomicAdd(&g_deg[dst], ew[e]);
    atomicAdd(&g_counts[dst], 1);
}

// ---------------- scan phase 1: per-chunk totals ----------------
__global__ void block_sum_kernel(int N) {
    __shared__ int warp_s[8];
    int base = blockIdx.x * SCAN_CHUNK;
    int tid = threadIdx.x;                 // 256 threads
    int s = 0;
#pragma unroll
    for (int i = 0; i < 4; i++) {
        int idx = base + tid + i * 256;
        if (idx < N) s += g_counts[idx];
    }
#pragma unroll
    for (int o = 16; o > 0; o >>= 1) s += __shfl_down_sync(0xffffffff, s, o);
    if ((tid & 31) == 0) warp_s[tid >> 5] = s;
    __syncthreads();
    if (tid < 8) {
        int v = warp_s[tid];
#pragma unroll
        for (int o = 4; o > 0; o >>= 1) v += __shfl_down_sync(0xff, v, o);
        if (tid == 0) g_bsum[blockIdx.x] = v;
    }
}

// ---------------- scan phase 2: exclusive scan of chunk totals ----------------
__global__ void scan_bsum_kernel(int N) {
    int tid = threadIdx.x;                 // 64 threads
    int v = (tid < SCAN_BLOCKS) ? g_bsum[tid] : 0;
    int orig = v;
    __shared__ int sh[64];
    sh[tid] = v;
    __syncthreads();
#pragma unroll
    for (int o = 1; o < 64; o <<= 1) {
        int t = (tid >= o) ? sh[tid - o] : 0;
        __syncthreads();
        sh[tid] += t;
        __syncthreads();
    }
    int excl = sh[tid] - orig;
    if (tid < SCAN_BLOCKS) g_bsum[tid] = excl;
    if (tid == SCAN_BLOCKS - 1) g_off[N] = excl + orig;   // grand total
}

// ---------------- scan phase 3: per-chunk scan + offset ----------------
__global__ void scan_final_kernel(int N) {
    __shared__ int warp_tot[32];
    int base = blockIdx.x * SCAN_CHUNK;
    int tid = threadIdx.x;                 // 1024 threads
    int lane = tid & 31, warp = tid >> 5;
    int i = base + tid;
    int v = (i < N) ? g_counts[i] : 0;
    int sv = v;
#pragma unroll
    for (int o = 1; o < 32; o <<= 1) {
        int t = __shfl_up_sync(0xffffffff, sv, o);
        if (lane >= o) sv += t;
    }
    if (lane == 31) warp_tot[warp] = sv;
    __syncthreads();
    if (warp == 0) {
        int w = warp_tot[lane];
        int sw = w;
#pragma unroll
        for (int o = 1; o < 32; o <<= 1) {
            int t = __shfl_up_sync(0xffffffff, sw, o);
            if (lane >= o) sw += t;
        }
        warp_tot[lane] = sw - w;           // exclusive warp offsets
    }
    __syncthreads();
    int excl = g_bsum[blockIdx.x] + warp_tot[warp] + sv - v;
    if (i < N) { g_off[i] = excl; g_cursor[i] = excl; }
}

// ---------------- norm + permutation into CSR slots ----------------
__global__ void permute_kernel(const void* __restrict__ ei, const float* __restrict__ ew, int E) {
    int e = blockIdx.x * blockDim.x + threadIdx.x;
    if (e >= E) return;
    int2 sd = load_edge(ei, e, E, g_is64);
    float ds = g_deg[sd.x], dd = g_deg[sd.y];
    float n = (ds > 0.0f && dd > 0.0f)
                  ? rsqrtf(fmaxf(ds, 1e-30f)) * ew[e] * rsqrtf(fmaxf(dd, 1e-30f))
                  : 0.0f;
    int pos = atomicAdd(&g_cursor[sd.y], 1);
    g_psrc[pos] = sd.x;
    g_pnorm[pos] = n;
}

// ---------------- packed f32x2 helpers ----------------
__device__ __forceinline__ unsigned long long pack2(float a) {
    unsigned long long r;
    asm("mov.b64 %0, {%1, %1};" : "=l"(r) : "f"(a));
    return r;
}
__device__ __forceinline__ void ffma2(unsigned long long& d, unsigned long long a, unsigned long long b) {
    asm("fma.rn.f32x2 %0, %1, %2, %3;" : "=l"(d) : "l"(a), "l"(b), "l"(d));
}
__device__ __forceinline__ float2 unpack2(unsigned long long v) {
    float2 u;
    asm("mov.b64 {%0, %1}, %2;" : "=f"(u.x), "=f"(u.y) : "l"(v));
    return u;
}

// ---------------- GEMM: C_half[N,128] = f(A)[N,128] @ W[128,128] ----------------
// Full W (64KB) + 64-row A tile (32KB) in dynamic smem. 256 threads,
// each computes 4 rows x 8 cols as 4x4 packed f32x2 accumulators.
// Output converted to fp16 (halves gather traffic in the following SpMM).
template <bool RELU_BIAS>
__global__ __launch_bounds__(256) void gemm_kernel(
    const float* __restrict__ A, const float* __restrict__ Wm,
    const float* __restrict__ bias, __half* __restrict__ C, int N)
{
    extern __shared__ float sm[];
    float* ws = sm;            // [128][128], k-major rows
    float* xs = sm + D * D;    // [64][128]

    int tid = threadIdx.x;
    int m_base = blockIdx.x * 64;

    // load W: 4096 float4 / 256 threads = 16 each
    const float4* W4 = (const float4*)Wm;
    float4* ws4 = (float4*)ws;
#pragma unroll
    for (int i = 0; i < 16; i++) ws4[tid + i * 256] = W4[tid + i * 256];

    // load A tile: 2048 float4 / 256 = 8 each (32 float4 per row)
    float4* xs4 = (float4*)xs;
#pragma unroll
    for (int i = 0; i < 8; i++) {
        int idx = tid + i * 256;
        int m = idx >> 5, c = idx & 31;
        int row = m_base + m;
        float4 v = make_float4(0.f, 0.f, 0.f, 0.f);
        if (row < N) v = ((const float4*)(A + (size_t)row * D))[c];
        if (RELU_BIAS) {
            float4 bb = ((const float4*)bias)[c];
            v.x = fmaxf(v.x + bb.x, 0.f);
            v.y = fmaxf(v.y + bb.y, 0.f);
            v.z = fmaxf(v.z + bb.z, 0.f);
            v.w = fmaxf(v.w + bb.w, 0.f);
        }
        xs4[idx] = v;
    }
    __syncthreads();

    int tx = tid & 15;         // f0 = tx*8 (4 f32x2 pairs)
    int ty = tid >> 4;         // m0 = ty*4
    int f0 = tx * 8;
    int m0 = ty * 4;

    unsigned long long acc[4][4];
#pragma unroll
    for (int i = 0; i < 4; i++)
#pragma unroll
        for (int j = 0; j < 4; j++) acc[i][j] = 0ull;

#pragma unroll 4
    for (int k = 0; k < D; k += 4) {
        float4 a4[4];
#pragma unroll
        for (int i = 0; i < 4; i++)
            a4[i] = *(const float4*)&xs[(m0 + i) * D + k];
#pragma unroll
        for (int kk = 0; kk < 4; kk++) {
            const unsigned long long* wrow =
                (const unsigned long long*)&ws[(k + kk) * D + f0];
            unsigned long long b0 = wrow[0], b1 = wrow[1], b2 = wrow[2], b3 = wrow[3];
#pragma unroll
            for (int i = 0; i < 4; i++) {
                float a = (kk == 0) ? a4[i].x : (kk == 1) ? a4[i].y : (kk == 2) ? a4[i].z : a4[i].w;
                unsigned long long ap = pack2(a);
                ffma2(acc[i][0], ap, b0);
                ffma2(acc[i][1], ap, b1);
                ffma2(acc[i][2], ap, b2);
                ffma2(acc[i][3], ap, b3);
            }
        }
    }

#pragma unroll
    for (int i = 0; i < 4; i++) {
        int row = m_base + m0 + i;
        if (row < N) {
            float2 p0 = unpack2(acc[i][0]);
            float2 p1 = unpack2(acc[i][1]);
            float2 p2 = unpack2(acc[i][2]);
            float2 p3 = unpack2(acc[i][3]);
            union { __half2 h[4]; uint4 u; } pk;
            pk.h[0] = __floats2half2_rn(p0.x, p0.y);
            pk.h[1] = __floats2half2_rn(p1.x, p1.y);
            pk.h[2] = __floats2half2_rn(p2.x, p2.y);
            pk.h[3] = __floats2half2_rn(p3.x, p3.y);
            *(uint4*)&C[(size_t)row * D + f0] = pk.u;
        }
    }
}

// ---------------- SpMM: out[i] = sum_j norm_j * h_half[src_j] (+ bias) ----------------
// one warp per dst node, 4 halfs (8B) per lane, fp32 accumulate, no atomics.
__global__ __launch_bounds__(256) void spmm_kernel(
    const __half* __restrict__ h, const float* __restrict__ bias,
    float* __restrict__ out, int N)
{
    int warp = (blockIdx.x * 256 + threadIdx.x) >> 5;
    if (warp >= N) return;
    int lane = threadIdx.x & 31;
    int beg = g_off[warp], end = g_off[warp + 1];

    float4 acc = make_float4(0.f, 0.f, 0.f, 0.f);
    int j = beg;
    for (; j + 2 <= end; j += 2) {
        int s0 = g_psrc[j], s1 = g_psrc[j + 1];
        float w0 = g_pnorm[j], w1 = g_pnorm[j + 1];
        uint2 u0 = ((const uint2*)(h + (size_t)s0 * D))[lane];
        uint2 u1 = ((const uint2*)(h + (size_t)s1 * D))[lane];
        float2 a0 = __half22float2(*(__half2*)&u0.x);
        float2 b0 = __half22float2(*(__half2*)&u0.y);
        float2 a1 = __half22float2(*(__half2*)&u1.x);
        float2 b1 = __half22float2(*(__half2*)&u1.y);
        acc.x = fmaf(a0.x, w0, fmaf(a1.x, w1, acc.x));
        acc.y = fmaf(a0.y, w0, fmaf(a1.y, w1, acc.y));
        acc.z = fmaf(b0.x, w0, fmaf(b1.x, w1, acc.z));
        acc.w = fmaf(b0.y, w0, fmaf(b1.y, w1, acc.w));
    }
    if (j < end) {
        int s0 = g_psrc[j];
        float w0 = g_pnorm[j];
        uint2 u0 = ((const uint2*)(h + (size_t)s0 * D))[lane];
        float2 a0 = __half22float2(*(__half2*)&u0.x);
        float2 b0 = __half22float2(*(__half2*)&u0.y);
        acc.x = fmaf(a0.x, w0, acc.x);
        acc.y = fmaf(a0.y, w0, acc.y);
        acc.z = fmaf(b0.x, w0, acc.z);
        acc.w = fmaf(b0.y, w0, acc.w);
    }
    if (bias != nullptr) {
        float4 b = ((const float4*)bias)[lane];
        acc.x += b.x; acc.y += b.y; acc.z += b.z; acc.w += b.w;
    }
    ((float4*)(out + (size_t)warp * D))[lane] = acc;
}

// ---------------- launch ----------------
extern "C" void kernel_launch(void* const* d_in, const int* in_sizes, int n_in,
                              void* d_out, int out_size) {
    const float* x  = (const float*)d_in[0];
    const void*  ei = d_in[1];
    const float* ew = (const float*)d_in[2];
    const float* W1 = (const float*)d_in[3];
    const float* b1 = (const float*)d_in[4];
    const float* W2 = (const float*)d_in[5];
    const float* b2 = (const float*)d_in[6];
    float* out = (float*)d_out;

    int N = in_sizes[0] / D;   // 50000
    int E = in_sizes[2];       // 800000

    __half* p_h = nullptr;
    float*  p_agg = nullptr;
    cudaGetSymbolAddress((void**)&p_h, g_h);
    cudaGetSymbolAddress((void**)&p_agg, g_agg);

    const int GEMM_SMEM = (D * D + 64 * D) * (int)sizeof(float);  // 96 KB
    cudaFuncSetAttribute(gemm_kernel<false>, cudaFuncAttributeMaxDynamicSharedMemorySize, GEMM_SMEM);
    cudaFuncSetAttribute(gemm_kernel<true>,  cudaFuncAttributeMaxDynamicSharedMemorySize, GEMM_SMEM);

    detect_kernel<<<1, 32>>>((const int*)ei);
    zero_kernel<<<(N + 255) / 256, 256>>>(N);
    deg_hist_kernel<<<(E + 255) / 256, 256>>>(ei, ew, E);
    block_sum_kernel<<<SCAN_BLOCKS, 256>>>(N);
    scan_bsum_kernel<<<1, 64>>>(N);
    scan_final_kernel<<<SCAN_BLOCKS, 1024>>>(N);
    permute_kernel<<<(E + 255) / 256, 256>>>(ei, ew, E);

    int gemm_blocks = (N + 63) / 64;
    int spmm_blocks = (N + 7) / 8;   // 8 warps/block, one warp per node

    // layer 1: h = fp16(x @ W1) ; agg = gatherSpMM(h)        (fp32 agg)
    gemm_kernel<false><<<gemm_blocks, 256, GEMM_SMEM>>>(x, W1, nullptr, p_h, N);
    spmm_kernel<<<spmm_blocks, 256>>>(p_h, nullptr, p_agg, N);

    // layer 2: h2 = fp16(relu(agg + b1) @ W2) ; out = gatherSpMM(h2) + b2
    gemm_kernel<true><<<gemm_blocks, 256, GEMM_SMEM>>>(p_agg, W2, b1, p_h, N);
    spmm_kernel<<<spmm_blocks, 256>>>(p_h, b2, out, N);
}

// round 7
// speedup vs baseline: 1.4956x; 1.4956x over previous
#include <cuda_runtime.h>
#include <cuda_fp16.h>
#include <cstdint>

#define NN 50000
#define EE 800000
#define D  128
#define SCAN_CHUNK 1024
#define SCAN_BLOCKS ((NN + SCAN_CHUNK - 1) / SCAN_CHUNK)   // 49

// ---------------- scratch (no allocations allowed) ----------------
__device__ float  g_deg[NN];          // weighted in-degree
__device__ int    g_counts[NN];       // edge count per dst
__device__ int    g_off[NN + 1];      // CSR offsets
__device__ int    g_cursor[NN];       // running cursor for permutation
__device__ int    g_bsum[SCAN_BLOCKS];// per-chunk totals (then exclusive-scanned)
__device__ int    g_psrc[EE];         // permuted src per CSR slot
__device__ float  g_pnorm[EE];        // permuted norm per CSR slot
__device__ __half g_h[NN * D];        // projection output in fp16 (both layers)
__device__ float  g_agg[NN * D];      // layer-1 aggregation target (fp32)
__device__ int    g_is64;             // 1 if edge_index is int64

// ---------------- dtype detection ----------------
// int64 indices (< 50000) viewed as int32 pairs => odd words all zero.
__global__ void detect_kernel(const int* __restrict__ ei) {
    if (threadIdx.x == 0 && blockIdx.x == 0) {
        int is64 = 1;
        for (int i = 0; i < 64; i++) {
            if (ei[2 * i + 1] != 0) { is64 = 0; break; }
        }
        g_is64 = is64;
    }
}

__device__ __forceinline__ int2 load_edge(const void* ei, int e, int E, int is64) {
    if (is64) {
        const long long* p = (const long long*)ei;
        return make_int2((int)p[e], (int)p[E + e]);
    } else {
        const int* p = (const int*)ei;
        return make_int2(p[e], p[E + e]);
    }
}

// ---------------- zero deg + counts ----------------
__global__ void zero_kernel(int N) {
    int i = blockIdx.x * blockDim.x + threadIdx.x;
    if (i < N) { g_deg[i] = 0.0f; g_counts[i] = 0; }
}

// ---------------- deg + histogram in one edge pass ----------------
__global__ void deg_hist_kernel(const void* __restrict__ ei, const float* __restrict__ ew, int E) {
    int e = blockIdx.x * blockDim.x + threadIdx.x;
    if (e >= E) return;
    int is64 = g_is64;
    int dst = is64 ? (int)((const long long*)ei)[E + e] : ((const int*)ei)[E + e];
    atomicAdd(&g_deg[dst], ew[e]);
    atomicAdd(&g_counts[dst], 1);
}

// ---------------- scan phase 1: per-chunk totals ----------------
__global__ void block_sum_kernel(int N) {
    __shared__ int warp_s[8];
    int base = blockIdx.x * SCAN_CHUNK;
    int tid = threadIdx.x;                 // 256 threads
    int s = 0;
#pragma unroll
    for (int i = 0; i < 4; i++) {
        int idx = base + tid + i * 256;
        if (idx < N) s += g_counts[idx];
    }
#pragma unroll
    for (int o = 16; o > 0; o >>= 1) s += __shfl_down_sync(0xffffffff, s, o);
    if ((tid & 31) == 0) warp_s[tid >> 5] = s;
    __syncthreads();
    if (tid < 8) {
        int v = warp_s[tid];
#pragma unroll
        for (int o = 4; o > 0; o >>= 1) v += __shfl_down_sync(0xff, v, o);
        if (tid == 0) g_bsum[blockIdx.x] = v;
    }
}

// ---------------- scan phase 2: exclusive scan of chunk totals ----------------
__global__ void scan_bsum_kernel(int N) {
    int tid = threadIdx.x;                 // 64 threads
    int v = (tid < SCAN_BLOCKS) ? g_bsum[tid] : 0;
    int orig = v;
    __shared__ int sh[64];
    sh[tid] = v;
    __syncthreads();
#pragma unroll
    for (int o = 1; o < 64; o <<= 1) {
        int t = (tid >= o) ? sh[tid - o] : 0;
        __syncthreads();
        sh[tid] += t;
        __syncthreads();
    }
    int excl = sh[tid] - orig;
    if (tid < SCAN_BLOCKS) g_bsum[tid] = excl;
    if (tid == SCAN_BLOCKS - 1) g_off[N] = excl + orig;   // grand total
}

// ---------------- scan phase 3: per-chunk scan + offset ----------------
__global__ void scan_final_kernel(int N) {
    __shared__ int warp_tot[32];
    int base = blockIdx.x * SCAN_CHUNK;
    int tid = threadIdx.x;                 // 1024 threads
    int lane = tid & 31, warp = tid >> 5;
    int i = base + tid;
    int v = (i < N) ? g_counts[i] : 0;
    int sv = v;
#pragma unroll
    for (int o = 1; o < 32; o <<= 1) {
        int t = __shfl_up_sync(0xffffffff, sv, o);
        if (lane >= o) sv += t;
    }
    if (lane == 31) warp_tot[warp] = sv;
    __syncthreads();
    if (warp == 0) {
        int w = warp_tot[lane];
        int sw = w;
#pragma unroll
        for (int o = 1; o < 32; o <<= 1) {
            int t = __shfl_up_sync(0xffffffff, sw, o);
            if (lane >= o) sw += t;
        }
        warp_tot[lane] = sw - w;           // exclusive warp offsets
    }
    __syncthreads();
    int excl = g_bsum[blockIdx.x] + warp_tot[warp] + sv - v;
    if (i < N) { g_off[i] = excl; g_cursor[i] = excl; }
}

// ---------------- norm + permutation into CSR slots ----------------
__global__ void permute_kernel(const void* __restrict__ ei, const float* __restrict__ ew, int E) {
    int e = blockIdx.x * blockDim.x + threadIdx.x;
    if (e >= E) return;
    int2 sd = load_edge(ei, e, E, g_is64);
    float ds = g_deg[sd.x], dd = g_deg[sd.y];
    float n = (ds > 0.0f && dd > 0.0f)
                  ? rsqrtf(fmaxf(ds, 1e-30f)) * ew[e] * rsqrtf(fmaxf(dd, 1e-30f))
                  : 0.0f;
    int pos = atomicAdd(&g_cursor[sd.y], 1);
    g_psrc[pos] = sd.x;
    g_pnorm[pos] = n;
}

// ---------------- packed f32x2 helpers ----------------
__device__ __forceinline__ unsigned long long pack2(float a) {
    unsigned long long r;
    asm("mov.b64 %0, {%1, %1};" : "=l"(r) : "f"(a));
    return r;
}
__device__ __forceinline__ void ffma2(unsigned long long& d, unsigned long long a, unsigned long long b) {
    asm("fma.rn.f32x2 %0, %1, %2, %3;" : "=l"(d) : "l"(a), "l"(b), "l"(d));
}
__device__ __forceinline__ float2 unpack2(unsigned long long v) {
    float2 u;
    asm("mov.b64 {%0, %1}, %2;" : "=f"(u.x), "=f"(u.y) : "l"(v));
    return u;
}

// ---------------- GEMM: C_half[N,128] = f(A)[N,128] @ W[128,128] ----------------
// Full W (64KB) + 64-row A tile (32KB) in dynamic smem. 256 threads,
// each computes 4 rows x 8 cols as 4x4 packed f32x2 accumulators.
// Output converted to fp16 (halves gather traffic in the following SpMM).
template <bool RELU_BIAS>
__global__ __launch_bounds__(256) void gemm_kernel(
    const float* __restrict__ A, const float* __restrict__ Wm,
    const float* __restrict__ bias, __half* __restrict__ C, int N)
{
    extern __shared__ float sm[];
    float* ws = sm;            // [128][128], k-major rows
    float* xs = sm + D * D;    // [64][128]

    int tid = threadIdx.x;
    int m_base = blockIdx.x * 64;

    // load W: 4096 float4 / 256 threads = 16 each
    const float4* W4 = (const float4*)Wm;
    float4* ws4 = (float4*)ws;
#pragma unroll
    for (int i = 0; i < 16; i++) ws4[tid + i * 256] = W4[tid + i * 256];

    // load A tile: 2048 float4 / 256 = 8 each (32 float4 per row)
    float4* xs4 = (float4*)xs;
#pragma unroll
    for (int i = 0; i < 8; i++) {
        int idx = tid + i * 256;
        int m = idx >> 5, c = idx & 31;
        int row = m_base + m;
        float4 v = make_float4(0.f, 0.f, 0.f, 0.f);
        if (row < N) v = ((const float4*)(A + (size_t)row * D))[c];
        if (RELU_BIAS) {
            float4 bb = ((const float4*)bias)[c];
            v.x = fmaxf(v.x + bb.x, 0.f);
            v.y = fmaxf(v.y + bb.y, 0.f);
            v.z = fmaxf(v.z + bb.z, 0.f);
            v.w = fmaxf(v.w + bb.w, 0.f);
        }
        xs4[idx] = v;
    }
    __syncthreads();

    int tx = tid & 15;         // f0 = tx*8 (4 f32x2 pairs)
    int ty = tid >> 4;         // m0 = ty*4
    int f0 = tx * 8;
    int m0 = ty * 4;

    unsigned long long acc[4][4];
#pragma unroll
    for (int i = 0; i < 4; i++)
#pragma unroll
        for (int j = 0; j < 4; j++) acc[i][j] = 0ull;

#pragma unroll 4
    for (int k = 0; k < D; k += 4) {
        float4 a4[4];
#pragma unroll
        for (int i = 0; i < 4; i++)
            a4[i] = *(const float4*)&xs[(m0 + i) * D + k];
#pragma unroll
        for (int kk = 0; kk < 4; kk++) {
            const unsigned long long* wrow =
                (const unsigned long long*)&ws[(k + kk) * D + f0];
            unsigned long long b0 = wrow[0], b1 = wrow[1], b2 = wrow[2], b3 = wrow[3];
#pragma unroll
            for (int i = 0; i < 4; i++) {
                float a = (kk == 0) ? a4[i].x : (kk == 1) ? a4[i].y : (kk == 2) ? a4[i].z : a4[i].w;
                unsigned long long ap = pack2(a);
                ffma2(acc[i][0], ap, b0);
                ffma2(acc[i][1], ap, b1);
                ffma2(acc[i][2], ap, b2);
                ffma2(acc[i][3], ap, b3);
            }
        }
    }

#pragma unroll
    for (int i = 0; i < 4; i++) {
        int row = m_base + m0 + i;
        if (row < N) {
            float2 p0 = unpack2(acc[i][0]);
            float2 p1 = unpack2(acc[i][1]);
            float2 p2 = unpack2(acc[i][2]);
            float2 p3 = unpack2(acc[i][3]);
            union { __half2 h[4]; uint4 u; } pk;
            pk.h[0] = __floats2half2_rn(p0.x, p0.y);
            pk.h[1] = __floats2half2_rn(p1.x, p1.y);
            pk.h[2] = __floats2half2_rn(p2.x, p2.y);
            pk.h[3] = __floats2half2_rn(p3.x, p3.y);
            *(uint4*)&C[(size_t)row * D + f0] = pk.u;
        }
    }
}

// ---------------- SpMM: out[i] = sum_j norm_j * h_half[src_j] (+ bias) ----------------
// one warp per dst node, 4 halfs (8B) per lane, fp32 accumulate, no atomics.
// 4-way unrolled with independent accumulator sets -> 4 outstanding gathers.
__device__ __forceinline__ void acc_half4(float4& acc, uint2 u, float w) {
    float2 a = __half22float2(*(__half2*)&u.x);
    float2 b = __half22float2(*(__half2*)&u.y);
    acc.x = fmaf(a.x, w, acc.x);
    acc.y = fmaf(a.y, w, acc.y);
    acc.z = fmaf(b.x, w, acc.z);
    acc.w = fmaf(b.y, w, acc.w);
}

__global__ __launch_bounds__(256) void spmm_kernel(
    const __half* __restrict__ h, const float* __restrict__ bias,
    float* __restrict__ out, int N)
{
    int warp = (blockIdx.x * 256 + threadIdx.x) >> 5;
    if (warp >= N) return;
    int lane = threadIdx.x & 31;
    int beg = g_off[warp], end = g_off[warp + 1];

    float4 acc0 = make_float4(0.f, 0.f, 0.f, 0.f);
    float4 acc1 = make_float4(0.f, 0.f, 0.f, 0.f);
    float4 acc2 = make_float4(0.f, 0.f, 0.f, 0.f);
    float4 acc3 = make_float4(0.f, 0.f, 0.f, 0.f);

    int j = beg;
    for (; j + 4 <= end; j += 4) {
        int s0 = g_psrc[j],     s1 = g_psrc[j + 1];
        int s2 = g_psrc[j + 2], s3 = g_psrc[j + 3];
        float w0 = g_pnorm[j],     w1 = g_pnorm[j + 1];
        float w2 = g_pnorm[j + 2], w3 = g_pnorm[j + 3];
        // 4 independent gathers in flight
        uint2 u0 = ((const uint2*)(h + (size_t)s0 * D))[lane];
        uint2 u1 = ((const uint2*)(h + (size_t)s1 * D))[lane];
        uint2 u2 = ((const uint2*)(h + (size_t)s2 * D))[lane];
        uint2 u3 = ((const uint2*)(h + (size_t)s3 * D))[lane];
        acc_half4(acc0, u0, w0);
        acc_half4(acc1, u1, w1);
        acc_half4(acc2, u2, w2);
        acc_half4(acc3, u3, w3);
    }
    for (; j < end; j++) {
        int s0 = g_psrc[j];
        float w0 = g_pnorm[j];
        uint2 u0 = ((const uint2*)(h + (size_t)s0 * D))[lane];
        acc_half4(acc0, u0, w0);
    }

    acc0.x += acc1.x; acc0.y += acc1.y; acc0.z += acc1.z; acc0.w += acc1.w;
    acc2.x += acc3.x; acc2.y += acc3.y; acc2.z += acc3.z; acc2.w += acc3.w;
    acc0.x += acc2.x; acc0.y += acc2.y; acc0.z += acc2.z; acc0.w += acc2.w;

    if (bias != nullptr) {
        float4 b = ((const float4*)bias)[lane];
        acc0.x += b.x; acc0.y += b.y; acc0.z += b.z; acc0.w += b.w;
    }
    ((float4*)(out + (size_t)warp * D))[lane] = acc0;
}

// ---------------- launch ----------------
extern "C" void kernel_launch(void* const* d_in, const int* in_sizes, int n_in,
                              void* d_out, int out_size) {
    const float* x  = (const float*)d_in[0];
    const void*  ei = d_in[1];
    const float* ew = (const float*)d_in[2];
    const float* W1 = (const float*)d_in[3];
    const float* b1 = (const float*)d_in[4];
    const float* W2 = (const float*)d_in[5];
    const float* b2 = (const float*)d_in[6];
    float* out = (float*)d_out;

    int N = in_sizes[0] / D;   // 50000
    int E = in_sizes[2];       // 800000

    __half* p_h = nullptr;
    float*  p_agg = nullptr;
    cudaGetSymbolAddress((void**)&p_h, g_h);
    cudaGetSymbolAddress((void**)&p_agg, g_agg);

    const int GEMM_SMEM = (D * D + 64 * D) * (int)sizeof(float);  // 96 KB
    cudaFuncSetAttribute(gemm_kernel<false>, cudaFuncAttributeMaxDynamicSharedMemorySize, GEMM_SMEM);
    cudaFuncSetAttribute(gemm_kernel<true>,  cudaFuncAttributeMaxDynamicSharedMemorySize, GEMM_SMEM);

    detect_kernel<<<1, 32>>>((const int*)ei);
    zero_kernel<<<(N + 255) / 256, 256>>>(N);
    deg_hist_kernel<<<(E + 255) / 256, 256>>>(ei, ew, E);
    block_sum_kernel<<<SCAN_BLOCKS, 256>>>(N);
    scan_bsum_kernel<<<1, 64>>>(N);
    scan_final_kernel<<<SCAN_BLOCKS, 1024>>>(N);
    permute_kernel<<<(E + 255) / 256, 256>>>(ei, ew, E);

    int gemm_blocks = (N + 63) / 64;
    int spmm_blocks = (N + 7) / 8;   // 8 warps/block, one warp per node

    // layer 1: h = fp16(x @ W1) ; agg = gatherSpMM(h)        (fp32 agg)
    gemm_kernel<false><<<gemm_blocks, 256, GEMM_SMEM>>>(x, W1, nullptr, p_h, N);
    spmm_kernel<<<spmm_blocks, 256>>>(p_h, nullptr, p_agg, N);

    // layer 2: h2 = fp16(relu(agg + b1) @ W2) ; out = gatherSpMM(h2) + b2
    gemm_kernel<true><<<gemm_blocks, 256, GEMM_SMEM>>>(p_agg, W2, b1, p_h, N);
    spmm_kernel<<<spmm_blocks, 256>>>(p_h, b2, out, N);
}